// round 10
// baseline (speedup 1.0000x reference)
#include <cuda_runtime.h>
#include <cuda_fp16.h>
#include <cstdint>
#include <math.h>

#define NN 4096
#define DD 64
#define LL 16
#define NT 32            // NN / 128 tiles per dim
#define NTRI 528         // NT*(NT+1)/2 triangular tile pairs
#define TILES_TOTAL (NTRI * LL * 2)
#define GRID_HY 296      // 148 tensor-role + 148 simt-role CTAs
#define SURV_CAP (1 << 20)
#define GATE 52.0f       // fp16-noise-safe gate (true cutoff 50, exp(-25) mass)
#define SMS 72           // tensor smem row stride (halves): conflict-free ldmatrix
#define KMS 136          // simt k-major row stride (halves)

// ---------------- device scratch (static, no allocation) ----------------
__device__ float  g_xp[2][LL][NN][DD];           // packed fp32 [mat][l][i][d]
__device__ __half g_xh[2][LL][NN][DD];           // packed f16 row-major
__device__ float  g_norm[2][LL][NN];             // squared norms (exact fp32)
__device__ float  g_r[2][LL][NN];                // row sums of K (init 1 = diag)
__device__ float  g_S[LL];                       // off-diag Sum Kx*Ky
__device__ int    g_scount;
__device__ int    g_wq;                          // shared tile work queue

struct Surv { int ml; int i; int j; };
__device__ Surv g_surv[SURV_CAP];

// ---------------- asm helpers (portable sm_80+ path) ----------------
__device__ __forceinline__ uint32_t smem_u32(const void* p) {
    uint32_t a;
    asm("{ .reg .u64 t; cvta.to.shared.u64 t, %1; cvt.u32.u64 %0, t; }"
        : "=r"(a) : "l"(p));
    return a;
}
__device__ __forceinline__ void ldsm_x4(uint32_t* r, uint32_t addr) {
    asm volatile("ldmatrix.sync.aligned.m8n8.x4.shared.b16 {%0,%1,%2,%3}, [%4];"
                 : "=r"(r[0]), "=r"(r[1]), "=r"(r[2]), "=r"(r[3]) : "r"(addr));
}
__device__ __forceinline__ void mma16816h(uint32_t* d, const uint32_t* a,
                                          uint32_t b0, uint32_t b1) {
    asm volatile("mma.sync.aligned.m16n8k16.row.col.f16.f16.f16.f16 "
                 "{%0,%1}, {%2,%3,%4,%5}, {%6,%7}, {%0,%1};"
                 : "+r"(d[0]), "+r"(d[1])
                 : "r"(a[0]), "r"(a[1]), "r"(a[2]), "r"(a[3]), "r"(b0), "r"(b1));
}

// decode flattened tile index -> (i0, j0, l, m)
__device__ __forceinline__ void decode_tile(int tix, int& i0, int& j0, int& l, int& m) {
    const int p = tix >> 5;          // lm minor for L2 reuse
    const int lm = tix & 31;
    l = lm >> 1; m = lm & 1;
    int it = (int)((2.0f * NT + 1.0f
                    - sqrtf((float)((2 * NT + 1) * (2 * NT + 1) - 8 * p))) * 0.5f);
    if (it < 0) it = 0; if (it > NT - 1) it = NT - 1;
    while (it > 0       && it * NT - (it * (it - 1)) / 2 > p) --it;
    while (it < NT - 1  && (it + 1) * NT - ((it + 1) * it) / 2 <= p) ++it;
    const int jt = it + (p - (it * NT - (it * (it - 1)) / 2));
    i0 = it * 128; j0 = jt * 128;
}

__device__ __forceinline__ void push_surv(int l, int m, int gi, int gj) {
    int s = atomicAdd(&g_scount, 1);
    if (s < SURV_CAP) {
        g_surv[s].ml = (l << 1) | m;
        g_surv[s].i = gi; g_surv[s].j = gj;
    }
}

// ---------------- init ----------------
__global__ void init_kernel() {
    int idx = blockIdx.x * blockDim.x + threadIdx.x;
    if (idx < 2 * LL * NN) ((float*)g_r)[idx] = 1.0f;
    if (idx < LL) g_S[idx] = 0.0f;
    if (idx == 0) { g_scount = 0; g_wq = 0; }
}

// ---------------- pack: (N, D, L) -> fp32 + f16 row-major + norms -----------
__global__ void pack_kernel(const float* __restrict__ X, const float* __restrict__ Y) {
    __shared__ float buf[DD * LL];      // buf[d*16 + l]
    const int m = blockIdx.y;
    const int i = blockIdx.x;
    const int t = threadIdx.x;
    const float* src = (m == 0 ? X : Y) + (size_t)i * (DD * LL);

#pragma unroll
    for (int q = 0; q < 4; ++q) buf[t + q * 256] = src[t + q * 256];
    __syncthreads();

#pragma unroll
    for (int q = 0; q < 4; ++q) {
        int e = t + q * 256;
        int l = e >> 6;
        int d = e & 63;
        float v = buf[d * LL + l];
        g_xp[m][l][i][d] = v;
        g_xh[m][l][i][d] = __float2half_rn(v);
    }
    if (t < LL) {
        float s = 0.0f;
#pragma unroll
        for (int d = 0; d < DD; ++d) { float v = buf[d * LL + t]; s = fmaf(v, v, s); }
        g_norm[m][t][i] = s;
    }
}

// ---------------- hybrid gram: tensor CTAs + HFMA2 SIMT CTAs, shared queue ---
__global__ void __launch_bounds__(256, 2) gram_kernel() {
    __shared__ __align__(16) uint8_t sm[37888];
    __shared__ float nIs[128], nJs[128];
    __shared__ int s_tix;

    const int t = threadIdx.x;
    const int lane = t & 31;
    const bool tensor_role = (blockIdx.x < 148);

    for (;;) {
        if (t == 0) s_tix = atomicAdd(&g_wq, 1);
        __syncthreads();
        const int tix = s_tix;
        if (tix >= TILES_TOTAL) return;

        int i0, j0, l, m;
        decode_tile(tix, i0, j0, l, m);

        if (tensor_role) {
            // ===================== tensor path (R9, proven) =====================
            __half* As = (__half*)sm;
            __half* Bs = (__half*)(sm + 18432);
            const int w = t >> 5;
            const int wm = w >> 2, wn = w & 3;
            const int qrow = lane >> 2, qc2 = (lane & 3) * 2;
            const int lrow = lane & 15, lcol = (lane >> 4) * 8;

            {
                const uint4* gA = (const uint4*)&g_xh[m][l][i0][0];
                const uint4* gB = (const uint4*)&g_xh[m][l][j0][0];
#pragma unroll
                for (int q = 0; q < 4; ++q) {
                    int idx = t + q * 256;
                    int row = idx >> 3, c16 = idx & 7;
                    *(uint4*)&As[row * SMS + c16 * 8] = gA[idx];
                    *(uint4*)&Bs[row * SMS + c16 * 8] = gB[idx];
                }
                if (t < 128) nIs[t] = g_norm[m][l][i0 + t];
                else         nJs[t - 128] = g_norm[m][l][j0 + t - 128];
            }
            __syncthreads();

            uint32_t acc[4][4][2];
#pragma unroll
            for (int a = 0; a < 4; ++a)
#pragma unroll
                for (int b = 0; b < 4; ++b) { acc[a][b][0] = 0u; acc[a][b][1] = 0u; }

            const uint32_t aBase = smem_u32(As);
            const uint32_t bBase = smem_u32(Bs);
#pragma unroll
            for (int ks = 0; ks < 4; ++ks) {
                const int kc = ks * 16;
                uint32_t af[4][4], bfr[2][4];
#pragma unroll
                for (int mf = 0; mf < 4; ++mf)
                    ldsm_x4(af[mf], aBase + ((wm * 64 + mf * 16 + lrow) * SMS + kc + lcol) * 2);
#pragma unroll
                for (int nb = 0; nb < 2; ++nb)
                    ldsm_x4(bfr[nb], bBase + ((wn * 32 + nb * 16 + lrow) * SMS + kc + lcol) * 2);
#pragma unroll
                for (int mf = 0; mf < 4; ++mf)
#pragma unroll
                    for (int j = 0; j < 4; ++j) {
                        const int nb = j >> 1, hi = j & 1;
                        mma16816h(acc[mf][j], af[mf], bfr[nb][hi], bfr[nb][2 + hi]);
                    }
            }

            float rmin[4], cmin[4];
#pragma unroll
            for (int mf = 0; mf < 4; ++mf)
                rmin[mf] = 0.5f * fminf(nIs[wm * 64 + mf * 16 + qrow],
                                        nIs[wm * 64 + mf * 16 + qrow + 8]);
#pragma unroll
            for (int j = 0; j < 4; ++j)
                cmin[j] = 0.5f * fminf(nJs[wn * 32 + j * 8 + qc2],
                                       nJs[wn * 32 + j * 8 + qc2 + 1]);

            uint32_t mask = 0;
#pragma unroll
            for (int mf = 0; mf < 4; ++mf)
#pragma unroll
                for (int j = 0; j < 4; ++j) {
                    __half2 h = __hmax2(*(__half2*)&acc[mf][j][0], *(__half2*)&acc[mf][j][1]);
                    float mx = fmaxf(__low2float(h), __high2float(h));
                    if (mx > rmin[mf] + cmin[j] - 0.5f * GATE) mask |= 1u << (mf * 4 + j);
                }

            if (mask) {
#pragma unroll
                for (int mf = 0; mf < 4; ++mf)
#pragma unroll
                    for (int j = 0; j < 4; ++j) {
                        if (!(mask & (1u << (mf * 4 + j)))) continue;
#pragma unroll
                        for (int r = 0; r < 4; ++r) {
                            const int li = wm * 64 + mf * 16 + qrow + ((r >> 1) << 3);
                            const int lj = wn * 32 + j * 8 + qc2 + (r & 1);
                            const int gi = i0 + li, gj = j0 + lj;
                            __half2 h2 = *(__half2*)&acc[mf][j][r >> 1];
                            float dotv = (r & 1) ? __high2float(h2) : __low2float(h2);
                            float d2 = nIs[li] + nJs[lj] - 2.0f * dotv;
                            if (gj > gi && d2 < GATE) push_surv(l, m, gi, gj);
                        }
                    }
            }
        } else {
            // ===================== SIMT path: HFMA2 on the FMA pipe =============
            // k-major smem: As[k][row], Bs[k][col], stride KMS halves
            __half* As = (__half*)sm;
            __half* Bs = (__half*)(sm + 17408);
            const int tx = t & 15, ty = t >> 4;
            const int mb = ty * 8, nb = tx * 8;

            {   // transpose fill: row-major global -> k-major smem
                const uint4* gA = (const uint4*)&g_xh[m][l][i0][0];
                const uint4* gB = (const uint4*)&g_xh[m][l][j0][0];
#pragma unroll
                for (int q4 = 0; q4 < 4; ++q4) {
                    int idx = t + q4 * 256;
                    int row = idx >> 3, d0 = (idx & 7) * 8;
                    uint4 va = gA[idx];
                    uint4 vb = gB[idx];
                    const __half* ha = (const __half*)&va;
                    const __half* hb = (const __half*)&vb;
#pragma unroll
                    for (int q = 0; q < 8; ++q) {
                        As[(d0 + q) * KMS + row] = ha[q];
                        Bs[(d0 + q) * KMS + row] = hb[q];
                    }
                }
                if (t < 128) nIs[t] = g_norm[m][l][i0 + t];
                else         nJs[t - 128] = g_norm[m][l][j0 + t - 128];
            }
            __syncthreads();

            __half2 acc[8][4];        // [row][colpair]; low=col nb+jp*2, high=+1
#pragma unroll
            for (int a = 0; a < 8; ++a)
#pragma unroll
                for (int b = 0; b < 4; ++b) acc[a][b] = __half2half2(__ushort_as_half(0));

#pragma unroll 8
            for (int k = 0; k < DD; ++k) {
                uint4 aq = *(const uint4*)&As[k * KMS + mb];   // 8 halves: rows mb..mb+7
                uint4 bq = *(const uint4*)&Bs[k * KMS + nb];   // 8 halves: cols nb..nb+7
                const uint32_t* ap = (const uint32_t*)&aq;
                __half2 bv[4] = { *(__half2*)&bq.x, *(__half2*)&bq.y,
                                  *(__half2*)&bq.z, *(__half2*)&bq.w };
#pragma unroll
                for (int mi = 0; mi < 8; ++mi) {
                    uint32_t bc = __byte_perm(ap[mi >> 1], ap[mi >> 1],
                                              (mi & 1) ? 0x3232 : 0x1010);
                    __half2 av = *(__half2*)&bc;
#pragma unroll
                    for (int jp = 0; jp < 4; ++jp)
                        acc[mi][jp] = __hfma2(av, bv[jp], acc[mi][jp]);
                }
            }

            // masked epilogue: one conservative test for the whole 8x8 block
            __half2 hm = acc[0][0];
#pragma unroll
            for (int mi = 0; mi < 8; ++mi)
#pragma unroll
                for (int jp = 0; jp < 4; ++jp) hm = __hmax2(hm, acc[mi][jp]);
            float mx = fmaxf(__low2float(hm), __high2float(hm));

            float rmin = nIs[mb];
#pragma unroll
            for (int q = 1; q < 8; ++q) rmin = fminf(rmin, nIs[mb + q]);
            float cmin = nJs[nb];
#pragma unroll
            for (int q = 1; q < 8; ++q) cmin = fminf(cmin, nJs[nb + q]);

            if (mx > 0.5f * (rmin + cmin) - 0.5f * GATE) {
#pragma unroll
                for (int mi = 0; mi < 8; ++mi) {
                    const int gi = i0 + mb + mi;
                    const float niv = nIs[mb + mi];
#pragma unroll
                    for (int jp = 0; jp < 4; ++jp) {
                        float d0v = __low2float(acc[mi][jp]);
                        float d1v = __high2float(acc[mi][jp]);
                        int gj0 = j0 + nb + jp * 2;
                        float d2a = niv + nJs[nb + jp * 2] - 2.0f * d0v;
                        float d2b = niv + nJs[nb + jp * 2 + 1] - 2.0f * d1v;
                        if (gj0 > gi && d2a < GATE)     push_surv(l, m, gi, gj0);
                        if (gj0 + 1 > gi && d2b < GATE) push_surv(l, m, gi, gj0 + 1);
                    }
                }
            }
        }

        __syncthreads();   // smem reads done before next tile's fill
    }
}

// ---------------- survivors: exact fp32 recompute + row sums + S -------------
__device__ __forceinline__ float dot64(const float* __restrict__ a, const float* __restrict__ b) {
    float s = 0.0f;
#pragma unroll
    for (int q = 0; q < 16; ++q) {
        float4 x = ((const float4*)a)[q];
        float4 y = ((const float4*)b)[q];
        s = fmaf(x.x, y.x, s); s = fmaf(x.y, y.y, s);
        s = fmaf(x.z, y.z, s); s = fmaf(x.w, y.w, s);
    }
    return s;
}

__global__ void surv_kernel() {
    int cnt = g_scount; if (cnt > SURV_CAP) cnt = SURV_CAP;
    for (int s = blockIdx.x * blockDim.x + threadIdx.x; s < cnt;
         s += gridDim.x * blockDim.x) {
        Surv v = g_surv[s];
        const int m = v.ml & 1;
        const int l = v.ml >> 1;
        const int om = m ^ 1;

        const float* bs = &g_xp[m][l][0][0];
        float d2s = g_norm[m][l][v.i] + g_norm[m][l][v.j]
                  - 2.0f * dot64(bs + (size_t)v.i * DD, bs + (size_t)v.j * DD);
        d2s = fmaxf(d2s, 0.0f);
        float val = __expf(-0.5f * d2s);
        atomicAdd(&g_r[m][l][v.i], val);
        atomicAdd(&g_r[m][l][v.j], val);

        const float* bo = &g_xp[om][l][0][0];
        float d2o = g_norm[om][l][v.i] + g_norm[om][l][v.j]
                  - 2.0f * dot64(bo + (size_t)v.i * DD, bo + (size_t)v.j * DD);
        d2o = fmaxf(d2o, 0.0f);
        if (m == 1 && d2o < GATE) continue;   // dedup: x-side owns double-gated pairs
        atomicAdd(&g_S[l], 2.0f * __expf(-0.5f * (d2s + d2o)));  // (i,j) and (j,i)
    }
}

// ---------------- finish: combine into HSIC sum ----------------
__global__ void finish_kernel(float* __restrict__ out) {
    __shared__ double sh0[256], sh1[256], sh2[256];
    const int t = threadIdx.x;
    double total = 0.0;
    const double n = (double)NN;

    for (int l = 0; l < LL; ++l) {
        const float* rx = &g_r[0][l][0];
        const float* ry = &g_r[1][l][0];
        double p = 0.0, sx = 0.0, sy = 0.0;
        for (int i = t; i < NN; i += 256) {
            double ax = (double)rx[i], ay = (double)ry[i];
            p += ax * ay; sx += ax; sy += ay;
        }
        sh0[t] = p; sh1[t] = sx; sh2[t] = sy;
        __syncthreads();
        for (int s = 128; s > 0; s >>= 1) {
            if (t < s) { sh0[t] += sh0[t + s]; sh1[t] += sh1[t + s]; sh2[t] += sh2[t + s]; }
            __syncthreads();
        }
        if (t == 0) {
            double S = n + (double)g_S[l];               // diagonal contributes n
            double num = S - 2.0 * sh0[0] / n + sh1[0] * sh2[0] / (n * n);
            total += num / ((n - 1.0) * (n - 1.0));
        }
        __syncthreads();
    }
    if (t == 0) out[0] = (float)total;
}

// ---------------- launch ----------------
extern "C" void kernel_launch(void* const* d_in, const int* in_sizes, int n_in,
                              void* d_out, int out_size) {
    const float* X = (const float*)d_in[0];
    const float* Y = (const float*)d_in[1];
    float* out = (float*)d_out;

    init_kernel<<<(2 * LL * NN + 255) / 256, 256>>>();
    pack_kernel<<<dim3(NN, 2), 256>>>(X, Y);
    gram_kernel<<<GRID_HY, 256>>>();
    surv_kernel<<<64, 256>>>();
    finish_kernel<<<1, 256>>>(out);
}

// round 12
// speedup vs baseline: 1.6547x; 1.6547x over previous
#include <cuda_runtime.h>
#include <cuda_fp16.h>
#include <cstdint>
#include <math.h>

#define NN 4096
#define DD 64
#define LL 16
#define NT 32            // NN / 128 tiles per dim
#define NTRI 528         // NT*(NT+1)/2 triangular tile pairs
#define SURV_CAP (1 << 20)
#define GATE 52.0f       // fp16-noise-safe gate (true cutoff 50, exp(-25) mass)
#define SMS 72           // padded smem row stride (f16 elems): conflict-free ldmatrix

// ---------------- device scratch (static, no allocation) ----------------
__device__ float  g_xp[2][LL][NN][DD];           // packed fp32 [mat][l][i][d]
__device__ __half g_xh[2][LL][NN][DD];           // packed f16 row-major
__device__ float  g_norm[2][LL][NN];             // squared norms (exact fp32)
__device__ float  g_r[2][LL][NN];                // row sums of K (init 1 = diag)
__device__ float  g_S[LL];                       // off-diag Sum Kx*Ky
__device__ int    g_scount;

struct Surv { int ml; int i; int j; };
__device__ Surv g_surv[SURV_CAP];

// ---------------- warp MMA helpers (portable sm_80+ path) ----------------
__device__ __forceinline__ uint32_t smem_u32(const void* p) {
    uint32_t a;
    asm("{ .reg .u64 t; cvta.to.shared.u64 t, %1; cvt.u32.u64 %0, t; }"
        : "=r"(a) : "l"(p));
    return a;
}
__device__ __forceinline__ void ldsm_x4(uint32_t* r, uint32_t addr) {
    asm volatile("ldmatrix.sync.aligned.m8n8.x4.shared.b16 {%0,%1,%2,%3}, [%4];"
                 : "=r"(r[0]), "=r"(r[1]), "=r"(r[2]), "=r"(r[3]) : "r"(addr));
}
// f16 inputs, f16 accumulators (2 packed regs)
__device__ __forceinline__ void mma16816h(uint32_t* d, const uint32_t* a,
                                          uint32_t b0, uint32_t b1) {
    asm volatile("mma.sync.aligned.m16n8k16.row.col.f16.f16.f16.f16 "
                 "{%0,%1}, {%2,%3,%4,%5}, {%6,%7}, {%0,%1};"
                 : "+r"(d[0]), "+r"(d[1])
                 : "r"(a[0]), "r"(a[1]), "r"(a[2]), "r"(a[3]), "r"(b0), "r"(b1));
}

// ---------------- pack: (N, D, L) -> fp32 + f16 + norms + init fold ----------
__global__ void pack_kernel(const float* __restrict__ X, const float* __restrict__ Y) {
    __shared__ float buf[DD * LL];      // buf[d*16 + l]
    const int m = blockIdx.y;
    const int i = blockIdx.x;
    const int t = threadIdx.x;
    const float* src = (m == 0 ? X : Y) + (size_t)i * (DD * LL);

#pragma unroll
    for (int q = 0; q < 4; ++q) buf[t + q * 256] = src[t + q * 256];

    // folded init (no dependence on buf; before the sync)
    if (m == 0 && i == 0) {
        if (t < LL) g_S[t] = 0.0f;
        if (t == 0) g_scount = 0;
    }
    __syncthreads();

#pragma unroll
    for (int q = 0; q < 4; ++q) {
        int e = t + q * 256;
        int l = e >> 6;
        int d = e & 63;
        float v = buf[d * LL + l];
        g_xp[m][l][i][d] = v;
        g_xh[m][l][i][d] = __float2half_rn(v);
    }
    if (t < LL) {
        float s = 0.0f;
#pragma unroll
        for (int d = 0; d < DD; ++d) { float v = buf[d * LL + t]; s = fmaf(v, v, s); }
        g_norm[m][t][i] = s;
        g_r[m][t][i] = 1.0f;            // row-sum init (diagonal term)
    }
}

// ---------------- main: 128x128x64 f16-accum HMMA Gram + masked epilogue -----
__global__ void __launch_bounds__(256, 2) gram_kernel() {
    // decode triangular tile pair (it <= jt)
    int p = blockIdx.x, it = 0, rem = NT;
    while (p >= rem) { p -= rem; rem--; it++; }
    const int jt = it + p;
    const int l = blockIdx.y;
    const int m = blockIdx.z;
    const int i0 = it * 128, j0 = jt * 128;

    __shared__ __align__(16) __half As[128 * SMS];
    __shared__ __align__(16) __half Bs[128 * SMS];
    __shared__ float nI[128], nJ[128];

    const int t = threadIdx.x;
    const int w = t >> 5;
    const int lane = t & 31;
    const int wm = w >> 2;            // 0..1  -> 64-row band
    const int wn = w & 3;             // 0..3  -> 32-col band
    const int qrow = lane >> 2;       // 0..7
    const int qc2 = (lane & 3) * 2;   // 0,2,4,6

    // fill smem tiles (row-major 64 -> padded 72)
    {
        const uint4* gA = (const uint4*)&g_xh[m][l][i0][0];   // 1024 chunks
        const uint4* gB = (const uint4*)&g_xh[m][l][j0][0];
#pragma unroll
        for (int q = 0; q < 4; ++q) {
            int idx = t + q * 256;
            int row = idx >> 3, c16 = idx & 7;
            *(uint4*)&As[row * SMS + c16 * 8] = gA[idx];
            *(uint4*)&Bs[row * SMS + c16 * 8] = gB[idx];
        }
        if (t < 128) nI[t] = g_norm[m][l][i0 + t];
        else         nJ[t - 128] = g_norm[m][l][j0 + t - 128];
    }
    __syncthreads();

    // diagonal tiles: warps whose whole 64x... sub-tile is strictly below the
    // diagonal (rows 64-127 x cols 0-63) can produce no survivors -> done.
    // (no further barriers in this kernel, so early exit is safe)
    if (it == jt && wm == 1 && wn < 2) return;

    uint32_t acc[4][4][2];            // [m-frag][n8-frag][row-group], half2 packed
#pragma unroll
    for (int a = 0; a < 4; ++a)
#pragma unroll
        for (int b = 0; b < 4; ++b) { acc[a][b][0] = 0u; acc[a][b][1] = 0u; }

    const int lrow = lane & 15;       // ldmatrix row select
    const int lcol = (lane >> 4) * 8; // ldmatrix col select (elements)

    const uint32_t aBase = smem_u32(As);
    const uint32_t bBase = smem_u32(Bs);

#pragma unroll
    for (int ks = 0; ks < 4; ++ks) {
        const int kc = ks * 16;
        uint32_t af[4][4], bfr[2][4];
#pragma unroll
        for (int mf = 0; mf < 4; ++mf)
            ldsm_x4(af[mf], aBase + ((wm * 64 + mf * 16 + lrow) * SMS + kc + lcol) * 2);
#pragma unroll
        for (int nb = 0; nb < 2; ++nb)
            ldsm_x4(bfr[nb], bBase + ((wn * 32 + nb * 16 + lrow) * SMS + kc + lcol) * 2);
#pragma unroll
        for (int mf = 0; mf < 4; ++mf)
#pragma unroll
            for (int j = 0; j < 4; ++j) {
                const int nb = j >> 1, hi = j & 1;
                mma16816h(acc[mf][j], af[mf], bfr[nb][hi], bfr[nb][2 + hi]);
            }
    }

    // ---- epilogue: conservative per-fragment mask, exact path only if hit ----
    float rmin[4], cmin[4];
#pragma unroll
    for (int mf = 0; mf < 4; ++mf)
        rmin[mf] = 0.5f * fminf(nI[wm * 64 + mf * 16 + qrow],
                                nI[wm * 64 + mf * 16 + qrow + 8]);
#pragma unroll
    for (int j = 0; j < 4; ++j)
        cmin[j] = 0.5f * fminf(nJ[wn * 32 + j * 8 + qc2],
                               nJ[wn * 32 + j * 8 + qc2 + 1]);

    uint32_t mask = 0;
#pragma unroll
    for (int mf = 0; mf < 4; ++mf)
#pragma unroll
        for (int j = 0; j < 4; ++j) {
            __half2 h = __hmax2(*(__half2*)&acc[mf][j][0], *(__half2*)&acc[mf][j][1]);
            float mx = fmaxf(__low2float(h), __high2float(h));
            // mx > 0.5*(nImin+nJmin) - GATE/2  <=>  min possible d2 < GATE
            if (mx > rmin[mf] + cmin[j] - 0.5f * GATE) mask |= 1u << (mf * 4 + j);
        }

    if (mask) {   // cold path: exact per-element gate + survivor append
#pragma unroll
        for (int mf = 0; mf < 4; ++mf) {
#pragma unroll
            for (int j = 0; j < 4; ++j) {
                if (!(mask & (1u << (mf * 4 + j)))) continue;
#pragma unroll
                for (int r = 0; r < 4; ++r) {
                    const int li = wm * 64 + mf * 16 + qrow + ((r >> 1) << 3);
                    const int lj = wn * 32 + j * 8 + qc2 + (r & 1);
                    const int gi = i0 + li;
                    const int gj = j0 + lj;
                    __half2 h2 = *(__half2*)&acc[mf][j][r >> 1];
                    float dotv = (r & 1) ? __high2float(h2) : __low2float(h2);
                    float d2 = nI[li] + nJ[lj] - 2.0f * dotv;
                    if (gj > gi && d2 < GATE) {
                        int s = atomicAdd(&g_scount, 1);
                        if (s < SURV_CAP) {
                            g_surv[s].ml = (l << 1) | m;
                            g_surv[s].i = gi; g_surv[s].j = gj;
                        }
                    }
                }
            }
        }
    }
}

// ---------------- survivors: exact fp32 recompute + row sums + S -------------
__device__ __forceinline__ float dot64(const float* __restrict__ a, const float* __restrict__ b) {
    float s = 0.0f;
#pragma unroll
    for (int q = 0; q < 16; ++q) {
        float4 x = ((const float4*)a)[q];
        float4 y = ((const float4*)b)[q];
        s = fmaf(x.x, y.x, s); s = fmaf(x.y, y.y, s);
        s = fmaf(x.z, y.z, s); s = fmaf(x.w, y.w, s);
    }
    return s;
}

__global__ void surv_kernel() {
    int cnt = g_scount; if (cnt > SURV_CAP) cnt = SURV_CAP;
    for (int s = blockIdx.x * blockDim.x + threadIdx.x; s < cnt;
         s += gridDim.x * blockDim.x) {
        Surv v = g_surv[s];
        const int m = v.ml & 1;
        const int l = v.ml >> 1;
        const int om = m ^ 1;

        const float* bs = &g_xp[m][l][0][0];
        float d2s = g_norm[m][l][v.i] + g_norm[m][l][v.j]
                  - 2.0f * dot64(bs + (size_t)v.i * DD, bs + (size_t)v.j * DD);
        d2s = fmaxf(d2s, 0.0f);
        float val = __expf(-0.5f * d2s);
        atomicAdd(&g_r[m][l][v.i], val);
        atomicAdd(&g_r[m][l][v.j], val);

        const float* bo = &g_xp[om][l][0][0];
        float d2o = g_norm[om][l][v.i] + g_norm[om][l][v.j]
                  - 2.0f * dot64(bo + (size_t)v.i * DD, bo + (size_t)v.j * DD);
        d2o = fmaxf(d2o, 0.0f);
        if (m == 1 && d2o < GATE) continue;   // dedup: x-side owns double-gated pairs
        atomicAdd(&g_S[l], 2.0f * __expf(-0.5f * (d2s + d2o)));  // (i,j) and (j,i)
    }
}

// ---------------- finish: combine into HSIC sum ----------------
__global__ void finish_kernel(float* __restrict__ out) {
    __shared__ double sh0[256], sh1[256], sh2[256];
    const int t = threadIdx.x;
    double total = 0.0;
    const double n = (double)NN;

    for (int l = 0; l < LL; ++l) {
        const float* rx = &g_r[0][l][0];
        const float* ry = &g_r[1][l][0];
        double p = 0.0, sx = 0.0, sy = 0.0;
        for (int i = t; i < NN; i += 256) {
            double ax = (double)rx[i], ay = (double)ry[i];
            p += ax * ay; sx += ax; sy += ay;
        }
        sh0[t] = p; sh1[t] = sx; sh2[t] = sy;
        __syncthreads();
        for (int s = 128; s > 0; s >>= 1) {
            if (t < s) { sh0[t] += sh0[t + s]; sh1[t] += sh1[t + s]; sh2[t] += sh2[t + s]; }
            __syncthreads();
        }
        if (t == 0) {
            double S = n + (double)g_S[l];               // diagonal contributes n
            double num = S - 2.0 * sh0[0] / n + sh1[0] * sh2[0] / (n * n);
            total += num / ((n - 1.0) * (n - 1.0));
        }
        __syncthreads();
    }
    if (t == 0) out[0] = (float)total;
}

// ---------------- launch ----------------
extern "C" void kernel_launch(void* const* d_in, const int* in_sizes, int n_in,
                              void* d_out, int out_size) {
    const float* X = (const float*)d_in[0];
    const float* Y = (const float*)d_in[1];
    float* out = (float*)d_out;

    pack_kernel<<<dim3(NN, 2), 256>>>(X, Y);
    gram_kernel<<<dim3(NTRI, LL, 2), 256>>>();
    surv_kernel<<<512, 256>>>();
    finish_kernel<<<1, 256>>>(out);
}

// round 14
// speedup vs baseline: 2.0753x; 1.2542x over previous
#include <cuda_runtime.h>
#include <cuda_fp16.h>
#include <cstdint>
#include <math.h>

#define NN 4096
#define DD 64
#define LL 16
#define NT 32            // NN / 128 tiles per dim
#define NTRI 528         // NT*(NT+1)/2 triangular tile pairs
#define SURV_CAP (1 << 20)
#define GATE 52.0f       // fp16-noise-safe gate (true cutoff 50, exp(-25) mass)
#define SMS 72           // padded smem row stride (f16 elems): conflict-free ldmatrix

// ---------------- device scratch (static, no allocation) ----------------
__device__ float  g_xp[2][LL][NN][DD];           // packed fp32 [mat][l][i][d]
__device__ __half g_xh[2][LL][NN][DD];           // packed f16 row-major
__device__ float  g_norm[2][LL][NN];             // squared norms (exact fp32)
__device__ float  g_r[2][LL][NN];                // row sums of K (init 1 = diag)
__device__ float  g_S[LL];                       // off-diag Sum Kx*Ky
__device__ double g_part[LL];                    // per-timestep HSIC partial
__device__ int    g_scount;

struct Surv { int ml; int i; int j; };
__device__ Surv g_surv[SURV_CAP];

// ---------------- warp MMA helpers (portable sm_80+ path) ----------------
__device__ __forceinline__ uint32_t smem_u32(const void* p) {
    uint32_t a;
    asm("{ .reg .u64 t; cvta.to.shared.u64 t, %1; cvt.u32.u64 %0, t; }"
        : "=r"(a) : "l"(p));
    return a;
}
__device__ __forceinline__ void ldsm_x4(uint32_t* r, uint32_t addr) {
    asm volatile("ldmatrix.sync.aligned.m8n8.x4.shared.b16 {%0,%1,%2,%3}, [%4];"
                 : "=r"(r[0]), "=r"(r[1]), "=r"(r[2]), "=r"(r[3]) : "r"(addr));
}
// f16 inputs, f16 accumulators (2 packed regs)
__device__ __forceinline__ void mma16816h(uint32_t* d, const uint32_t* a,
                                          uint32_t b0, uint32_t b1) {
    asm volatile("mma.sync.aligned.m16n8k16.row.col.f16.f16.f16.f16 "
                 "{%0,%1}, {%2,%3,%4,%5}, {%6,%7}, {%0,%1};"
                 : "+r"(d[0]), "+r"(d[1])
                 : "r"(a[0]), "r"(a[1]), "r"(a[2]), "r"(a[3]), "r"(b0), "r"(b1));
}

// ---------------- pack: (N, D, L) -> fp32 + f16 + norms + init fold ----------
__global__ void pack_kernel(const float* __restrict__ X, const float* __restrict__ Y) {
    __shared__ float buf[DD * LL];      // buf[d*16 + l]
    const int m = blockIdx.y;
    const int i = blockIdx.x;
    const int t = threadIdx.x;
    const float* src = (m == 0 ? X : Y) + (size_t)i * (DD * LL);

#pragma unroll
    for (int q = 0; q < 4; ++q) buf[t + q * 256] = src[t + q * 256];

    // folded init (no dependence on buf; before the sync)
    if (m == 0 && i == 0) {
        if (t < LL) g_S[t] = 0.0f;
        if (t == 0) g_scount = 0;
    }
    __syncthreads();

#pragma unroll
    for (int q = 0; q < 4; ++q) {
        int e = t + q * 256;
        int l = e >> 6;
        int d = e & 63;
        float v = buf[d * LL + l];
        g_xp[m][l][i][d] = v;
        g_xh[m][l][i][d] = __float2half_rn(v);
    }
    if (t < LL) {
        float s = 0.0f;
#pragma unroll
        for (int d = 0; d < DD; ++d) { float v = buf[d * LL + t]; s = fmaf(v, v, s); }
        g_norm[m][t][i] = s;
        g_r[m][t][i] = 1.0f;            // row-sum init (diagonal term)
    }
}

// ---------------- main: 128x128x64 f16-accum HMMA Gram + masked epilogue -----
__global__ void __launch_bounds__(256, 2) gram_kernel() {
    // decode triangular tile pair (it <= jt)
    int p = blockIdx.x, it = 0, rem = NT;
    while (p >= rem) { p -= rem; rem--; it++; }
    const int jt = it + p;
    const int l = blockIdx.y;
    const int m = blockIdx.z;
    const int i0 = it * 128, j0 = jt * 128;

    __shared__ __align__(16) __half As[128 * SMS];
    __shared__ __align__(16) __half Bs[128 * SMS];
    __shared__ float nI[128], nJ[128];

    const int t = threadIdx.x;
    const int w = t >> 5;
    const int lane = t & 31;
    const int wm = w >> 2;            // 0..1  -> 64-row band
    const int wn = w & 3;             // 0..3  -> 32-col band
    const int qrow = lane >> 2;       // 0..7
    const int qc2 = (lane & 3) * 2;   // 0,2,4,6

    // fill smem tiles (row-major 64 -> padded 72)
    {
        const uint4* gA = (const uint4*)&g_xh[m][l][i0][0];   // 1024 chunks
        const uint4* gB = (const uint4*)&g_xh[m][l][j0][0];
#pragma unroll
        for (int q = 0; q < 4; ++q) {
            int idx = t + q * 256;
            int row = idx >> 3, c16 = idx & 7;
            *(uint4*)&As[row * SMS + c16 * 8] = gA[idx];
            *(uint4*)&Bs[row * SMS + c16 * 8] = gB[idx];
        }
        if (t < 128) nI[t] = g_norm[m][l][i0 + t];
        else         nJ[t - 128] = g_norm[m][l][j0 + t - 128];
    }
    __syncthreads();

    // diagonal tiles: warps whose whole sub-tile is strictly below the
    // diagonal can produce no survivors -> done.
    if (it == jt && wm == 1 && wn < 2) return;

    uint32_t acc[4][4][2];            // [m-frag][n8-frag][row-group], half2 packed
#pragma unroll
    for (int a = 0; a < 4; ++a)
#pragma unroll
        for (int b = 0; b < 4; ++b) { acc[a][b][0] = 0u; acc[a][b][1] = 0u; }

    const int lrow = lane & 15;       // ldmatrix row select
    const int lcol = (lane >> 4) * 8; // ldmatrix col select (elements)

    const uint32_t aBase = smem_u32(As);
    const uint32_t bBase = smem_u32(Bs);

#pragma unroll
    for (int ks = 0; ks < 4; ++ks) {
        const int kc = ks * 16;
        uint32_t af[4][4], bfr[2][4];
#pragma unroll
        for (int mf = 0; mf < 4; ++mf)
            ldsm_x4(af[mf], aBase + ((wm * 64 + mf * 16 + lrow) * SMS + kc + lcol) * 2);
#pragma unroll
        for (int nb = 0; nb < 2; ++nb)
            ldsm_x4(bfr[nb], bBase + ((wn * 32 + nb * 16 + lrow) * SMS + kc + lcol) * 2);
#pragma unroll
        for (int mf = 0; mf < 4; ++mf)
#pragma unroll
            for (int j = 0; j < 4; ++j) {
                const int nb = j >> 1, hi = j & 1;
                mma16816h(acc[mf][j], af[mf], bfr[nb][hi], bfr[nb][2 + hi]);
            }
    }

    // ---- epilogue: conservative per-fragment mask, exact path only if hit ----
    float rmin[4], cmin[4];
#pragma unroll
    for (int mf = 0; mf < 4; ++mf)
        rmin[mf] = 0.5f * fminf(nI[wm * 64 + mf * 16 + qrow],
                                nI[wm * 64 + mf * 16 + qrow + 8]);
#pragma unroll
    for (int j = 0; j < 4; ++j)
        cmin[j] = 0.5f * fminf(nJ[wn * 32 + j * 8 + qc2],
                               nJ[wn * 32 + j * 8 + qc2 + 1]);

    uint32_t mask = 0;
#pragma unroll
    for (int mf = 0; mf < 4; ++mf)
#pragma unroll
        for (int j = 0; j < 4; ++j) {
            __half2 h = __hmax2(*(__half2*)&acc[mf][j][0], *(__half2*)&acc[mf][j][1]);
            float mx = fmaxf(__low2float(h), __high2float(h));
            // mx > 0.5*(nImin+nJmin) - GATE/2  <=>  min possible d2 < GATE
            if (mx > rmin[mf] + cmin[j] - 0.5f * GATE) mask |= 1u << (mf * 4 + j);
        }

    if (mask) {   // cold path: exact per-element gate + survivor append
#pragma unroll
        for (int mf = 0; mf < 4; ++mf) {
#pragma unroll
            for (int j = 0; j < 4; ++j) {
                if (!(mask & (1u << (mf * 4 + j)))) continue;
#pragma unroll
                for (int r = 0; r < 4; ++r) {
                    const int li = wm * 64 + mf * 16 + qrow + ((r >> 1) << 3);
                    const int lj = wn * 32 + j * 8 + qc2 + (r & 1);
                    const int gi = i0 + li;
                    const int gj = j0 + lj;
                    __half2 h2 = *(__half2*)&acc[mf][j][r >> 1];
                    float dotv = (r & 1) ? __high2float(h2) : __low2float(h2);
                    float d2 = nI[li] + nJ[lj] - 2.0f * dotv;
                    if (gj > gi && d2 < GATE) {
                        int s = atomicAdd(&g_scount, 1);
                        if (s < SURV_CAP) {
                            g_surv[s].ml = (l << 1) | m;
                            g_surv[s].i = gi; g_surv[s].j = gj;
                        }
                    }
                }
            }
        }
    }
}

// ---------------- survivors: exact fp32 recompute + row sums + S -------------
__device__ __forceinline__ float dot64(const float* __restrict__ a, const float* __restrict__ b) {
    float s = 0.0f;
#pragma unroll
    for (int q = 0; q < 16; ++q) {
        float4 x = ((const float4*)a)[q];
        float4 y = ((const float4*)b)[q];
        s = fmaf(x.x, y.x, s); s = fmaf(x.y, y.y, s);
        s = fmaf(x.z, y.z, s); s = fmaf(x.w, y.w, s);
    }
    return s;
}

__global__ void surv_kernel() {
    int cnt = g_scount; if (cnt > SURV_CAP) cnt = SURV_CAP;
    for (int s = blockIdx.x * blockDim.x + threadIdx.x; s < cnt;
         s += gridDim.x * blockDim.x) {
        Surv v = g_surv[s];
        const int m = v.ml & 1;
        const int l = v.ml >> 1;
        const int om = m ^ 1;

        const float* bs = &g_xp[m][l][0][0];
        float d2s = g_norm[m][l][v.i] + g_norm[m][l][v.j]
                  - 2.0f * dot64(bs + (size_t)v.i * DD, bs + (size_t)v.j * DD);
        d2s = fmaxf(d2s, 0.0f);
        float val = __expf(-0.5f * d2s);
        atomicAdd(&g_r[m][l][v.i], val);
        atomicAdd(&g_r[m][l][v.j], val);

        const float* bo = &g_xp[om][l][0][0];
        float d2o = g_norm[om][l][v.i] + g_norm[om][l][v.j]
                  - 2.0f * dot64(bo + (size_t)v.i * DD, bo + (size_t)v.j * DD);
        d2o = fmaxf(d2o, 0.0f);
        if (m == 1 && d2o < GATE) continue;   // dedup: x-side owns double-gated pairs
        atomicAdd(&g_S[l], 2.0f * __expf(-0.5f * (d2s + d2o)));  // (i,j) and (j,i)
    }
}

// ---------------- finish stage 1: one block per timestep l -------------------
__global__ void finish_kernel() {
    __shared__ double sh0[256], sh1[256], sh2[256];
    const int t = threadIdx.x;
    const int l = blockIdx.x;
    const double n = (double)NN;

    const float* rx = &g_r[0][l][0];
    const float* ry = &g_r[1][l][0];
    double p = 0.0, sx = 0.0, sy = 0.0;
    for (int i = t; i < NN; i += 256) {
        double ax = (double)rx[i], ay = (double)ry[i];
        p += ax * ay; sx += ax; sy += ay;
    }
    sh0[t] = p; sh1[t] = sx; sh2[t] = sy;
    __syncthreads();
    for (int s = 128; s > 0; s >>= 1) {
        if (t < s) { sh0[t] += sh0[t + s]; sh1[t] += sh1[t + s]; sh2[t] += sh2[t + s]; }
        __syncthreads();
    }
    if (t == 0) {
        double S = n + (double)g_S[l];                   // diagonal contributes n
        double num = S - 2.0 * sh0[0] / n + sh1[0] * sh2[0] / (n * n);
        g_part[l] = num / ((n - 1.0) * (n - 1.0));
    }
}

// ---------------- finish stage 2: deterministic l-ordered sum ----------------
__global__ void final_kernel(float* __restrict__ out) {
    if (threadIdx.x == 0) {
        double total = 0.0;
        for (int l = 0; l < LL; ++l) total += g_part[l];  // same order as before
        out[0] = (float)total;
    }
}

// ---------------- launch ----------------
extern "C" void kernel_launch(void* const* d_in, const int* in_sizes, int n_in,
                              void* d_out, int out_size) {
    const float* X = (const float*)d_in[0];
    const float* Y = (const float*)d_in[1];
    float* out = (float*)d_out;

    pack_kernel<<<dim3(NN, 2), 256>>>(X, Y);
    gram_kernel<<<dim3(NTRI, LL, 2), 256>>>();
    surv_kernel<<<512, 256>>>();
    finish_kernel<<<LL, 256>>>();
    final_kernel<<<1, 32>>>(out);
}